// round 6
// baseline (speedup 1.0000x reference)
#include <cuda_runtime.h>
#include <cstdint>

// ---------------------------------------------------------------------------
// GCN 4-layer, CSR-gather formulation (no float atomics):
//   h   = out_norm[m] * (act @ W)          (SGEMM + epilogue)   -> g_h
//   act = relu( in_norm[d] * sum_{e: dst=d} g_h[src_e] + b )    (warp gather)
// edge_index is INT32 (jax x64 disabled): ei[0..E)=src, ei[E..2E)=dst.
// ---------------------------------------------------------------------------

#define NN_MAX 50000
#define EE_MAX 800000

__device__ __align__(16) float g_h  [NN_MAX * 128]; // gemm output (messages)
__device__ __align__(16) float g_act[NN_MAX * 128]; // layer activation
__device__ float g_non[NN_MAX];     // out-degree norm (src side)
__device__ float g_nin[NN_MAX];     // in-degree norm (dst side)
__device__ int   g_cout[NN_MAX];    // out-degree counts
__device__ int   g_cin [NN_MAX];    // in-degree counts
__device__ int   g_off [NN_MAX + 1];// CSR row offsets (by dst)
__device__ int   g_cur [NN_MAX];    // fill cursors
__device__ int   g_csrc[EE_MAX];    // CSR column = src node per in-edge

// --------------------------- degrees / norms --------------------------------

__global__ void zero_counts_kernel(int n) {
    int i = blockIdx.x * blockDim.x + threadIdx.x;
    if (i < n) { g_cout[i] = 0; g_cin[i] = 0; }
}

__global__ void count_deg_kernel(const int* __restrict__ ei, int E) {
    int i = blockIdx.x * blockDim.x + threadIdx.x;
    if (i >= 2 * E) return;
    int v = ei[i];
    if (i < E) atomicAdd(&g_cout[v], 1);
    else       atomicAdd(&g_cin[v], 1);
}

__global__ void make_norms_kernel(int n) {
    int i = blockIdx.x * blockDim.x + threadIdx.x;
    if (i < n) {
        g_non[i] = rsqrtf(fmaxf((float)g_cout[i], 1.0f));
        g_nin[i] = rsqrtf(fmaxf((float)g_cin[i],  1.0f));
    }
}

// --------------------------- prefix sum (single block) ----------------------

__global__ void scan_offsets_kernel(int n) {
    __shared__ int sh[1024];
    __shared__ int carry_sh;
    const int tid = threadIdx.x;
    if (tid == 0) carry_sh = 0;
    __syncthreads();
    for (int base = 0; base < n; base += 1024) {
        int i = base + tid;
        int v = (i < n) ? g_cin[i] : 0;
        sh[tid] = v;
        __syncthreads();
#pragma unroll
        for (int ofs = 1; ofs < 1024; ofs <<= 1) {
            int add = (tid >= ofs) ? sh[tid - ofs] : 0;
            __syncthreads();
            sh[tid] += add;
            __syncthreads();
        }
        int c = carry_sh;                       // uniform
        if (i < n) g_off[i] = c + sh[tid] - v;  // exclusive
        __syncthreads();
        if (tid == 1023) carry_sh = c + sh[1023];
        __syncthreads();
    }
    if (tid == 0) g_off[n] = carry_sh;
}

__global__ void copy_cursor_kernel(int n) {
    int i = blockIdx.x * blockDim.x + threadIdx.x;
    if (i < n) g_cur[i] = g_off[i];
}

__global__ void fill_csr_kernel(const int* __restrict__ ei, int E) {
    int e = blockIdx.x * blockDim.x + threadIdx.x;
    if (e >= E) return;
    int s = ei[e];
    int d = ei[E + e];
    int pos = atomicAdd(&g_cur[d], 1);
    g_csrc[pos] = s;
}

// --------------------------- GEMM with row-scale epilogue -------------------
// g_h[m][n] = g_non[m] * sum_k A[m][k] * W[k][n]

template<int K, int N, bool A_FROM_ACT>
__global__ void __launch_bounds__(256, 2) gemm_rowscale_kernel(
    const float* __restrict__ Ap, const float* __restrict__ W, int M)
{
    constexpr int TM = 128;
    constexpr int KT = 16;
    constexpr int CPT = N / 16; // 8 for N=128, 4 for N=64

    const float* __restrict__ A = A_FROM_ACT ? g_act : Ap;

    __shared__ float As[KT][TM + 4];           // scalar access (padded)
    __shared__ __align__(16) float Ws[KT][N];  // float4 access

    const int tid = threadIdx.x;
    const int tx = tid & 15;
    const int ty = tid >> 4;
    const int m0 = blockIdx.x * TM;

    float acc[8][CPT];
#pragma unroll
    for (int j = 0; j < 8; j++)
#pragma unroll
        for (int c = 0; c < CPT; c++) acc[j][c] = 0.0f;

    for (int k0 = 0; k0 < K; k0 += KT) {
#pragma unroll
        for (int i = 0; i < (TM * KT) / 256; i++) {
            int idx = tid + i * 256;
            int m = idx >> 4;
            int k = idx & 15;
            int gm = m0 + m;
            float v = 0.0f;
            if (gm < M) v = A[(size_t)gm * K + (k0 + k)];
            As[k][m] = v;
        }
#pragma unroll
        for (int i = 0; i < (KT * N) / 256; i++) {
            int idx = tid + i * 256;
            int kk = idx / N;
            int c  = idx % N;
            Ws[kk][c] = W[(size_t)(k0 + kk) * N + c];
        }
        __syncthreads();

#pragma unroll
        for (int kk = 0; kk < KT; kk++) {
            float a[8];
            float w[CPT];
#pragma unroll
            for (int j = 0; j < 8; j++) a[j] = As[kk][ty * 8 + j];
            const float4* wp = reinterpret_cast<const float4*>(&Ws[kk][tx * CPT]);
            float4 w0 = wp[0];
            w[0] = w0.x; w[1] = w0.y; w[2] = w0.z; w[3] = w0.w;
            if (CPT == 8) {
                float4 w1 = wp[1];
                w[4] = w1.x; w[5] = w1.y; w[6] = w1.z; w[7] = w1.w;
            }
#pragma unroll
            for (int j = 0; j < 8; j++)
#pragma unroll
                for (int c = 0; c < CPT; c++)
                    acc[j][c] = fmaf(a[j], w[c], acc[j][c]);
        }
        __syncthreads();
    }

#pragma unroll
    for (int j = 0; j < 8; j++) {
        int gm = m0 + ty * 8 + j;
        if (gm < M) {
            float s = g_non[gm];
            float4 o0;
            o0.x = acc[j][0] * s; o0.y = acc[j][1] * s;
            o0.z = acc[j][2] * s; o0.w = acc[j][3] * s;
            float4* cp = reinterpret_cast<float4*>(&g_h[(size_t)gm * N + tx * CPT]);
            cp[0] = o0;
            if (CPT == 8) {
                float4 o1;
                o1.x = acc[j][4] * s; o1.y = acc[j][5] * s;
                o1.z = acc[j][6] * s; o1.w = acc[j][7] * s;
                cp[1] = o1;
            }
        }
    }
}

// --------------------------- gather-aggregate --------------------------------
// One warp per dst node. Lane owns N/32 consecutive features; loop over
// in-edges, read g_h[src] row (coalesced 512B/256B, L2-resident), accumulate
// in registers, then fuse in_norm * acc + bias (+relu) and store.

template<int N, bool RELU, bool TO_PARAM>
__global__ void aggregate_kernel(const float* __restrict__ bias,
                                 float* __restrict__ outp, int M) {
    constexpr int VPL = N / 32;  // floats per lane: 4 (N=128) or 2 (N=64)
    int warp = (blockIdx.x * blockDim.x + threadIdx.x) >> 5;
    if (warp >= M) return;
    int lane = threadIdx.x & 31;

    int beg = g_off[warp];
    int end = g_off[warp + 1];

    float acc[VPL];
#pragma unroll
    for (int c = 0; c < VPL; c++) acc[c] = 0.0f;

    int e = beg;
    for (; e + 1 < end; e += 2) {   // unroll-by-2 for MLP
        int s0 = g_csrc[e];
        int s1 = g_csrc[e + 1];
        if (VPL == 4) {
            float4 v0 = *reinterpret_cast<const float4*>(g_h + (size_t)s0 * N + lane * 4);
            float4 v1 = *reinterpret_cast<const float4*>(g_h + (size_t)s1 * N + lane * 4);
            acc[0] += v0.x + v1.x; acc[1] += v0.y + v1.y;
            acc[2] += v0.z + v1.z; acc[3] += v0.w + v1.w;
        } else {
            float2 v0 = *reinterpret_cast<const float2*>(g_h + (size_t)s0 * N + lane * 2);
            float2 v1 = *reinterpret_cast<const float2*>(g_h + (size_t)s1 * N + lane * 2);
            acc[0] += v0.x + v1.x; acc[1] += v0.y + v1.y;
        }
    }
    if (e < end) {
        int s0 = g_csrc[e];
        if (VPL == 4) {
            float4 v0 = *reinterpret_cast<const float4*>(g_h + (size_t)s0 * N + lane * 4);
            acc[0] += v0.x; acc[1] += v0.y; acc[2] += v0.z; acc[3] += v0.w;
        } else {
            float2 v0 = *reinterpret_cast<const float2*>(g_h + (size_t)s0 * N + lane * 2);
            acc[0] += v0.x; acc[1] += v0.y;
        }
    }

    float s = g_nin[warp];
    float* out = TO_PARAM ? outp : g_act;
    if (VPL == 4) {
        float4 b = reinterpret_cast<const float4*>(bias)[lane];
        float4 o;
        o.x = acc[0] * s + b.x; o.y = acc[1] * s + b.y;
        o.z = acc[2] * s + b.z; o.w = acc[3] * s + b.w;
        if (RELU) {
            o.x = fmaxf(o.x, 0.f); o.y = fmaxf(o.y, 0.f);
            o.z = fmaxf(o.z, 0.f); o.w = fmaxf(o.w, 0.f);
        }
        *reinterpret_cast<float4*>(out + (size_t)warp * N + lane * 4) = o;
    } else {
        float2 b = reinterpret_cast<const float2*>(bias)[lane];
        float2 o;
        o.x = acc[0] * s + b.x; o.y = acc[1] * s + b.y;
        if (RELU) { o.x = fmaxf(o.x, 0.f); o.y = fmaxf(o.y, 0.f); }
        *reinterpret_cast<float2*>(out + (size_t)warp * N + lane * 2) = o;
    }
}

// --------------------------- launch ------------------------------------------

extern "C" void kernel_launch(void* const* d_in, const int* in_sizes, int n_in,
                              void* d_out, int out_size) {
    const float* x  = (const float*)d_in[0];
    const int*   ei = (const int*)d_in[1];          // int32 edge_index!
    const float* W0 = (const float*)d_in[2];
    const float* b0 = (const float*)d_in[3];
    const float* W1 = (const float*)d_in[4];
    const float* b1 = (const float*)d_in[5];
    const float* W2 = (const float*)d_in[6];
    const float* b2 = (const float*)d_in[7];
    const float* W3 = (const float*)d_in[8];
    const float* b3 = (const float*)d_in[9];
    float* out = (float*)d_out;

    const int M = in_sizes[0] / 256;   // 50000 nodes
    const int E = in_sizes[1] / 2;     // 800000 edges
    const int T = 256;

    // ---- graph preprocessing: degrees, norms, CSR by dst
    zero_counts_kernel<<<(M + T - 1) / T, T>>>(M);
    count_deg_kernel<<<(2 * E + T - 1) / T, T>>>(ei, E);
    make_norms_kernel<<<(M + T - 1) / T, T>>>(M);
    scan_offsets_kernel<<<1, 1024>>>(M);
    copy_cursor_kernel<<<(M + T - 1) / T, T>>>(M);
    fill_csr_kernel<<<(E + T - 1) / T, T>>>(ei, E);

    const int gemm_blocks = (M + 127) / 128;
    const int agg_blocks  = (M * 32 + T - 1) / T;

    // ---- layer 0: 256 -> 128, relu
    gemm_rowscale_kernel<256, 128, false><<<gemm_blocks, 256>>>(x, W0, M);
    aggregate_kernel<128, true, false><<<agg_blocks, T>>>(b0, nullptr, M);

    // ---- layer 1: 128 -> 128, relu
    gemm_rowscale_kernel<128, 128, true><<<gemm_blocks, 256>>>(nullptr, W1, M);
    aggregate_kernel<128, true, false><<<agg_blocks, T>>>(b1, nullptr, M);

    // ---- layer 2: 128 -> 128, relu
    gemm_rowscale_kernel<128, 128, true><<<gemm_blocks, 256>>>(nullptr, W2, M);
    aggregate_kernel<128, true, false><<<agg_blocks, T>>>(b2, nullptr, M);

    // ---- layer 3: 128 -> 64, no relu, write d_out
    gemm_rowscale_kernel<128, 64, true><<<gemm_blocks, 256>>>(nullptr, W3, M);
    aggregate_kernel<64, false, true><<<agg_blocks, T>>>(b3, out, M);
}

// round 7
// speedup vs baseline: 1.0571x; 1.0571x over previous
#include <cuda_runtime.h>
#include <cstdint>

// ---------------------------------------------------------------------------
// GCN 4-layer, CSR-gather formulation (no float atomics):
//   h   = out_norm[m] * (act @ W)          (SGEMM + epilogue)   -> g_h
//   act = relu( in_norm[d] * sum_{e: dst=d} g_h[src_e] + b )    (warp gather)
// edge_index is INT32: ei[0..E)=src, ei[E..2E)=dst.
// ---------------------------------------------------------------------------

#define NN_MAX 50000
#define EE_MAX 800000

__device__ __align__(16) float g_h  [NN_MAX * 128]; // gemm output (messages)
__device__ __align__(16) float g_act[NN_MAX * 128]; // layer activation
__device__ float g_non[NN_MAX];     // out-degree norm (src side)
__device__ float g_nin[NN_MAX];     // in-degree norm (dst side)
__device__ int   g_cout[NN_MAX];    // out-degree counts
__device__ int   g_cin [NN_MAX];    // in-degree counts
__device__ int   g_off [NN_MAX + 1];// CSR row offsets (by dst)
__device__ int   g_cur [NN_MAX];    // fill cursors
__device__ int   g_csrc[EE_MAX];    // CSR column = src node per in-edge

// --------------------------- degrees / norms --------------------------------

__global__ void zero_counts_kernel(int n) {
    int i = blockIdx.x * blockDim.x + threadIdx.x;
    if (i < n) { g_cout[i] = 0; g_cin[i] = 0; }
}

__global__ void count_deg_kernel(const int* __restrict__ ei, int E) {
    int i = blockIdx.x * blockDim.x + threadIdx.x;
    if (i >= 2 * E) return;
    int v = ei[i];
    if (i < E) atomicAdd(&g_cout[v], 1);
    else       atomicAdd(&g_cin[v], 1);
}

__global__ void make_norms_kernel(int n) {
    int i = blockIdx.x * blockDim.x + threadIdx.x;
    if (i < n) {
        g_non[i] = rsqrtf(fmaxf((float)g_cout[i], 1.0f));
        g_nin[i] = rsqrtf(fmaxf((float)g_cin[i],  1.0f));
    }
}

// --------------------------- prefix sum (single block, shuffle scan) --------
// Exclusive scan of g_cin into g_off (and g_cur). 1024 threads, warp-shuffle
// intra-warp scan + 32-wide spine scan; 3 barriers per 1024-chunk.

__global__ void scan_offsets_kernel(int n) {
    __shared__ int sh_warp[32];
    __shared__ int sh_carry;
    const int tid  = threadIdx.x;
    const int lane = tid & 31;
    const int wid  = tid >> 5;

    if (tid == 0) sh_carry = 0;
    __syncthreads();

    for (int base = 0; base < n; base += 1024) {
        int i = base + tid;
        int v = (i < n) ? g_cin[i] : 0;

        // intra-warp inclusive scan
        int incl = v;
#pragma unroll
        for (int ofs = 1; ofs < 32; ofs <<= 1) {
            int t = __shfl_up_sync(0xffffffffu, incl, ofs);
            if (lane >= ofs) incl += t;
        }
        if (lane == 31) sh_warp[wid] = incl;
        __syncthreads();

        // spine scan of 32 warp totals (warp 0)
        if (wid == 0) {
            int w = sh_warp[lane];
            int wi = w;
#pragma unroll
            for (int ofs = 1; ofs < 32; ofs <<= 1) {
                int t = __shfl_up_sync(0xffffffffu, wi, ofs);
                if (lane >= ofs) wi += t;
            }
            sh_warp[lane] = wi - w;   // exclusive warp prefix
        }
        __syncthreads();

        int carry = sh_carry;
        int excl = carry + sh_warp[wid] + incl - v;
        if (i < n) { g_off[i] = excl; g_cur[i] = excl; }
        __syncthreads();
        if (tid == 1023) sh_carry = excl + v;   // block total + old carry
        __syncthreads();
    }
    if (tid == 0) g_off[n] = sh_carry;
}

__global__ void fill_csr_kernel(const int* __restrict__ ei, int E) {
    int e = blockIdx.x * blockDim.x + threadIdx.x;
    if (e >= E) return;
    int s = ei[e];
    int d = ei[E + e];
    int pos = atomicAdd(&g_cur[d], 1);
    g_csrc[pos] = s;
}

// --------------------------- GEMM with row-scale epilogue -------------------
// g_h[m][n] = g_non[m] * sum_k A[m][k] * W[k][n]

template<int K, int N, bool A_FROM_ACT>
__global__ void __launch_bounds__(256, 2) gemm_rowscale_kernel(
    const float* __restrict__ Ap, const float* __restrict__ W, int M)
{
    constexpr int TM = 128;
    constexpr int KT = 16;
    constexpr int CPT = N / 16; // 8 for N=128, 4 for N=64

    const float* __restrict__ A = A_FROM_ACT ? g_act : Ap;

    __shared__ float As[KT][TM + 4];           // scalar access (padded)
    __shared__ __align__(16) float Ws[KT][N];  // float4 access

    const int tid = threadIdx.x;
    const int tx = tid & 15;
    const int ty = tid >> 4;
    const int m0 = blockIdx.x * TM;

    float acc[8][CPT];
#pragma unroll
    for (int j = 0; j < 8; j++)
#pragma unroll
        for (int c = 0; c < CPT; c++) acc[j][c] = 0.0f;

    for (int k0 = 0; k0 < K; k0 += KT) {
#pragma unroll
        for (int i = 0; i < (TM * KT) / 256; i++) {
            int idx = tid + i * 256;
            int m = idx >> 4;
            int k = idx & 15;
            int gm = m0 + m;
            float v = 0.0f;
            if (gm < M) v = A[(size_t)gm * K + (k0 + k)];
            As[k][m] = v;
        }
#pragma unroll
        for (int i = 0; i < (KT * N) / 256; i++) {
            int idx = tid + i * 256;
            int kk = idx / N;
            int c  = idx % N;
            Ws[kk][c] = W[(size_t)(k0 + kk) * N + c];
        }
        __syncthreads();

#pragma unroll
        for (int kk = 0; kk < KT; kk++) {
            float a[8];
            float w[CPT];
#pragma unroll
            for (int j = 0; j < 8; j++) a[j] = As[kk][ty * 8 + j];
            const float4* wp = reinterpret_cast<const float4*>(&Ws[kk][tx * CPT]);
            float4 w0 = wp[0];
            w[0] = w0.x; w[1] = w0.y; w[2] = w0.z; w[3] = w0.w;
            if (CPT == 8) {
                float4 w1 = wp[1];
                w[4] = w1.x; w[5] = w1.y; w[6] = w1.z; w[7] = w1.w;
            }
#pragma unroll
            for (int j = 0; j < 8; j++)
#pragma unroll
                for (int c = 0; c < CPT; c++)
                    acc[j][c] = fmaf(a[j], w[c], acc[j][c]);
        }
        __syncthreads();
    }

#pragma unroll
    for (int j = 0; j < 8; j++) {
        int gm = m0 + ty * 8 + j;
        if (gm < M) {
            float s = g_non[gm];
            float4 o0;
            o0.x = acc[j][0] * s; o0.y = acc[j][1] * s;
            o0.z = acc[j][2] * s; o0.w = acc[j][3] * s;
            float4* cp = reinterpret_cast<float4*>(&g_h[(size_t)gm * N + tx * CPT]);
            cp[0] = o0;
            if (CPT == 8) {
                float4 o1;
                o1.x = acc[j][4] * s; o1.y = acc[j][5] * s;
                o1.z = acc[j][6] * s; o1.w = acc[j][7] * s;
                cp[1] = o1;
            }
        }
    }
}

// --------------------------- gather-aggregate --------------------------------
// One warp per dst node; lane owns N/32 consecutive floats; rows L2-resident.

template<int N, bool RELU, bool TO_PARAM>
__global__ void aggregate_kernel(const float* __restrict__ bias,
                                 float* __restrict__ outp, int M) {
    constexpr int VPL = N / 32;  // 4 (N=128) or 2 (N=64)
    int warp = (blockIdx.x * blockDim.x + threadIdx.x) >> 5;
    if (warp >= M) return;
    int lane = threadIdx.x & 31;

    int beg = g_off[warp];
    int end = g_off[warp + 1];

    float acc[VPL];
#pragma unroll
    for (int c = 0; c < VPL; c++) acc[c] = 0.0f;

    int e = beg;
    for (; e + 1 < end; e += 2) {   // unroll-by-2 for MLP
        int s0 = g_csrc[e];
        int s1 = g_csrc[e + 1];
        if (VPL == 4) {
            float4 v0 = *reinterpret_cast<const float4*>(g_h + (size_t)s0 * N + lane * 4);
            float4 v1 = *reinterpret_cast<const float4*>(g_h + (size_t)s1 * N + lane * 4);
            acc[0] += v0.x + v1.x; acc[1] += v0.y + v1.y;
            acc[2] += v0.z + v1.z; acc[3] += v0.w + v1.w;
        } else {
            float2 v0 = *reinterpret_cast<const float2*>(g_h + (size_t)s0 * N + lane * 2);
            float2 v1 = *reinterpret_cast<const float2*>(g_h + (size_t)s1 * N + lane * 2);
            acc[0] += v0.x + v1.x; acc[1] += v0.y + v1.y;
        }
    }
    if (e < end) {
        int s0 = g_csrc[e];
        if (VPL == 4) {
            float4 v0 = *reinterpret_cast<const float4*>(g_h + (size_t)s0 * N + lane * 4);
            acc[0] += v0.x; acc[1] += v0.y; acc[2] += v0.z; acc[3] += v0.w;
        } else {
            float2 v0 = *reinterpret_cast<const float2*>(g_h + (size_t)s0 * N + lane * 2);
            acc[0] += v0.x; acc[1] += v0.y;
        }
    }

    float s = g_nin[warp];
    float* out = TO_PARAM ? outp : g_act;
    if (VPL == 4) {
        float4 b = reinterpret_cast<const float4*>(bias)[lane];
        float4 o;
        o.x = acc[0] * s + b.x; o.y = acc[1] * s + b.y;
        o.z = acc[2] * s + b.z; o.w = acc[3] * s + b.w;
        if (RELU) {
            o.x = fmaxf(o.x, 0.f); o.y = fmaxf(o.y, 0.f);
            o.z = fmaxf(o.z, 0.f); o.w = fmaxf(o.w, 0.f);
        }
        *reinterpret_cast<float4*>(out + (size_t)warp * N + lane * 4) = o;
    } else {
        float2 b = reinterpret_cast<const float2*>(bias)[lane];
        float2 o;
        o.x = acc[0] * s + b.x; o.y = acc[1] * s + b.y;
        if (RELU) { o.x = fmaxf(o.x, 0.f); o.y = fmaxf(o.y, 0.f); }
        *reinterpret_cast<float2*>(out + (size_t)warp * N + lane * 2) = o;
    }
}

// --------------------------- launch ------------------------------------------

extern "C" void kernel_launch(void* const* d_in, const int* in_sizes, int n_in,
                              void* d_out, int out_size) {
    const float* x  = (const float*)d_in[0];
    const int*   ei = (const int*)d_in[1];          // int32 edge_index
    const float* W0 = (const float*)d_in[2];
    const float* b0 = (const float*)d_in[3];
    const float* W1 = (const float*)d_in[4];
    const float* b1 = (const float*)d_in[5];
    const float* W2 = (const float*)d_in[6];
    const float* b2 = (const float*)d_in[7];
    const float* W3 = (const float*)d_in[8];
    const float* b3 = (const float*)d_in[9];
    float* out = (float*)d_out;

    const int M = in_sizes[0] / 256;   // 50000 nodes
    const int E = in_sizes[1] / 2;     // 800000 edges
    const int T = 256;

    // ---- graph preprocessing: degrees, norms, CSR by dst
    zero_counts_kernel<<<(M + T - 1) / T, T>>>(M);
    count_deg_kernel<<<(2 * E + T - 1) / T, T>>>(ei, E);
    make_norms_kernel<<<(M + T - 1) / T, T>>>(M);
    scan_offsets_kernel<<<1, 1024>>>(M);            // also fills g_cur
    fill_csr_kernel<<<(E + T - 1) / T, T>>>(ei, E);

    const int gemm_blocks = (M + 127) / 128;
    const int agg_blocks  = (M * 32 + T - 1) / T;

    // ---- layer 0: 256 -> 128, relu
    gemm_rowscale_kernel<256, 128, false><<<gemm_blocks, 256>>>(x, W0, M);
    aggregate_kernel<128, true, false><<<agg_blocks, T>>>(b0, nullptr, M);

    // ---- layer 1: 128 -> 128, relu
    gemm_rowscale_kernel<128, 128, true><<<gemm_blocks, 256>>>(nullptr, W1, M);
    aggregate_kernel<128, true, false><<<agg_blocks, T>>>(b1, nullptr, M);

    // ---- layer 2: 128 -> 128, relu
    gemm_rowscale_kernel<128, 128, true><<<gemm_blocks, 256>>>(nullptr, W2, M);
    aggregate_kernel<128, true, false><<<agg_blocks, T>>>(b2, nullptr, M);

    // ---- layer 3: 128 -> 64, no relu, write d_out
    gemm_rowscale_kernel<128, 64, true><<<gemm_blocks, 256>>>(nullptr, W3, M);
    aggregate_kernel<64, false, true><<<agg_blocks, T>>>(b3, out, M);
}

// round 8
// speedup vs baseline: 1.1119x; 1.0519x over previous
#include <cuda_runtime.h>
#include <cstdint>

// ---------------------------------------------------------------------------
// GCN 4-layer, CSR-gather formulation (no float atomics):
//   h   = out_norm[m] * (act @ W)          (SGEMM + epilogue)   -> g_h
//   act = relu( in_norm[d] * sum_{e: dst=d} g_h[src_e] + b )    (warp gather)
// edge_index is INT32: ei[0..E)=src, ei[E..2E)=dst.
// CSR buckets allocated by atomic bump (disjoint, unordered) - no prefix scan.
// ---------------------------------------------------------------------------

#define NN_MAX 50000
#define EE_MAX 800000

__device__ __align__(16) float g_h  [NN_MAX * 128]; // gemm output (messages)
__device__ __align__(16) float g_act[NN_MAX * 128]; // layer activation
__device__ float g_non[NN_MAX];     // out-degree norm (src side)
__device__ float g_nin[NN_MAX];     // in-degree norm (dst side)
__device__ int   g_cout[NN_MAX];    // out-degree counts
__device__ int   g_cin [NN_MAX];    // in-degree counts
__device__ int   g_off [NN_MAX];    // CSR bucket start (by dst)
__device__ int   g_cur [NN_MAX];    // fill cursors
__device__ int   g_csrc[EE_MAX];    // CSR column = src node per in-edge
__device__ int   g_total;           // bump allocator

// --------------------------- degrees ----------------------------------------

__global__ void zero_counts_kernel(int n) {
    int i = blockIdx.x * blockDim.x + threadIdx.x;
    if (i < n) { g_cout[i] = 0; g_cin[i] = 0; }
    if (i == 0) g_total = 0;
}

__global__ void count_deg_kernel(const int* __restrict__ ei, int E) {
    int i = blockIdx.x * blockDim.x + threadIdx.x;
    if (i >= 2 * E) return;
    int v = ei[i];
    if (i < E) atomicAdd(&g_cout[v], 1);
    else       atomicAdd(&g_cin[v], 1);
}

// --------------------------- norms + bucket allocation ----------------------
// Disjoint CSR buckets via atomic bump allocation (order irrelevant for the
// gather); fuses rsqrt norm computation. Replaces the serial prefix scan.

__global__ void norms_alloc_kernel(int n) {
    int i = blockIdx.x * blockDim.x + threadIdx.x;
    if (i >= n) return;
    int cin  = g_cin[i];
    int cout = g_cout[i];
    g_non[i] = rsqrtf(fmaxf((float)cout, 1.0f));
    g_nin[i] = rsqrtf(fmaxf((float)cin,  1.0f));
    int beg = atomicAdd(&g_total, cin);
    g_off[i] = beg;
    g_cur[i] = beg;
}

__global__ void fill_csr_kernel(const int* __restrict__ ei, int E) {
    int e = blockIdx.x * blockDim.x + threadIdx.x;
    if (e >= E) return;
    int s = ei[e];
    int d = ei[E + e];
    int pos = atomicAdd(&g_cur[d], 1);
    g_csrc[pos] = s;
}

// --------------------------- GEMM with row-scale epilogue -------------------
// g_h[m][n] = g_non[m] * sum_k A[m][k] * W[k][n]

template<int K, int N, bool A_FROM_ACT>
__global__ void __launch_bounds__(256, 2) gemm_rowscale_kernel(
    const float* __restrict__ Ap, const float* __restrict__ W, int M)
{
    constexpr int TM = 128;
    constexpr int KT = 16;
    constexpr int CPT = N / 16; // 8 for N=128, 4 for N=64

    const float* __restrict__ A = A_FROM_ACT ? g_act : Ap;

    __shared__ float As[KT][TM + 4];           // scalar access (padded)
    __shared__ __align__(16) float Ws[KT][N];  // float4 access

    const int tid = threadIdx.x;
    const int tx = tid & 15;
    const int ty = tid >> 4;
    const int m0 = blockIdx.x * TM;

    float acc[8][CPT];
#pragma unroll
    for (int j = 0; j < 8; j++)
#pragma unroll
        for (int c = 0; c < CPT; c++) acc[j][c] = 0.0f;

    for (int k0 = 0; k0 < K; k0 += KT) {
#pragma unroll
        for (int i = 0; i < (TM * KT) / 256; i++) {
            int idx = tid + i * 256;
            int m = idx >> 4;
            int k = idx & 15;
            int gm = m0 + m;
            float v = 0.0f;
            if (gm < M) v = A[(size_t)gm * K + (k0 + k)];
            As[k][m] = v;
        }
#pragma unroll
        for (int i = 0; i < (KT * N) / 256; i++) {
            int idx = tid + i * 256;
            int kk = idx / N;
            int c  = idx % N;
            Ws[kk][c] = W[(size_t)(k0 + kk) * N + c];
        }
        __syncthreads();

#pragma unroll
        for (int kk = 0; kk < KT; kk++) {
            float a[8];
            float w[CPT];
#pragma unroll
            for (int j = 0; j < 8; j++) a[j] = As[kk][ty * 8 + j];
            const float4* wp = reinterpret_cast<const float4*>(&Ws[kk][tx * CPT]);
            float4 w0 = wp[0];
            w[0] = w0.x; w[1] = w0.y; w[2] = w0.z; w[3] = w0.w;
            if (CPT == 8) {
                float4 w1 = wp[1];
                w[4] = w1.x; w[5] = w1.y; w[6] = w1.z; w[7] = w1.w;
            }
#pragma unroll
            for (int j = 0; j < 8; j++)
#pragma unroll
                for (int c = 0; c < CPT; c++)
                    acc[j][c] = fmaf(a[j], w[c], acc[j][c]);
        }
        __syncthreads();
    }

#pragma unroll
    for (int j = 0; j < 8; j++) {
        int gm = m0 + ty * 8 + j;
        if (gm < M) {
            float s = g_non[gm];
            float4 o0;
            o0.x = acc[j][0] * s; o0.y = acc[j][1] * s;
            o0.z = acc[j][2] * s; o0.w = acc[j][3] * s;
            float4* cp = reinterpret_cast<float4*>(&g_h[(size_t)gm * N + tx * CPT]);
            cp[0] = o0;
            if (CPT == 8) {
                float4 o1;
                o1.x = acc[j][4] * s; o1.y = acc[j][5] * s;
                o1.z = acc[j][6] * s; o1.w = acc[j][7] * s;
                cp[1] = o1;
            }
        }
    }
}

// --------------------------- gather-aggregate --------------------------------
// One warp per dst node; lane owns N/32 consecutive floats; rows L2-resident.

template<int N, bool RELU, bool TO_PARAM>
__global__ void aggregate_kernel(const float* __restrict__ bias,
                                 float* __restrict__ outp, int M) {
    constexpr int VPL = N / 32;  // 4 (N=128) or 2 (N=64)
    int warp = (blockIdx.x * blockDim.x + threadIdx.x) >> 5;
    if (warp >= M) return;
    int lane = threadIdx.x & 31;

    int beg = g_off[warp];
    int end = beg + g_cin[warp];

    float acc[VPL];
#pragma unroll
    for (int c = 0; c < VPL; c++) acc[c] = 0.0f;

    int e = beg;
    for (; e + 1 < end; e += 2) {   // unroll-by-2 for MLP
        int s0 = g_csrc[e];
        int s1 = g_csrc[e + 1];
        if (VPL == 4) {
            float4 v0 = *reinterpret_cast<const float4*>(g_h + (size_t)s0 * N + lane * 4);
            float4 v1 = *reinterpret_cast<const float4*>(g_h + (size_t)s1 * N + lane * 4);
            acc[0] += v0.x + v1.x; acc[1] += v0.y + v1.y;
            acc[2] += v0.z + v1.z; acc[3] += v0.w + v1.w;
        } else {
            float2 v0 = *reinterpret_cast<const float2*>(g_h + (size_t)s0 * N + lane * 2);
            float2 v1 = *reinterpret_cast<const float2*>(g_h + (size_t)s1 * N + lane * 2);
            acc[0] += v0.x + v1.x; acc[1] += v0.y + v1.y;
        }
    }
    if (e < end) {
        int s0 = g_csrc[e];
        if (VPL == 4) {
            float4 v0 = *reinterpret_cast<const float4*>(g_h + (size_t)s0 * N + lane * 4);
            acc[0] += v0.x; acc[1] += v0.y; acc[2] += v0.z; acc[3] += v0.w;
        } else {
            float2 v0 = *reinterpret_cast<const float2*>(g_h + (size_t)s0 * N + lane * 2);
            acc[0] += v0.x; acc[1] += v0.y;
        }
    }

    float s = g_nin[warp];
    float* out = TO_PARAM ? outp : g_act;
    if (VPL == 4) {
        float4 b = reinterpret_cast<const float4*>(bias)[lane];
        float4 o;
        o.x = acc[0] * s + b.x; o.y = acc[1] * s + b.y;
        o.z = acc[2] * s + b.z; o.w = acc[3] * s + b.w;
        if (RELU) {
            o.x = fmaxf(o.x, 0.f); o.y = fmaxf(o.y, 0.f);
            o.z = fmaxf(o.z, 0.f); o.w = fmaxf(o.w, 0.f);
        }
        *reinterpret_cast<float4*>(out + (size_t)warp * N + lane * 4) = o;
    } else {
        float2 b = reinterpret_cast<const float2*>(bias)[lane];
        float2 o;
        o.x = acc[0] * s + b.x; o.y = acc[1] * s + b.y;
        if (RELU) { o.x = fmaxf(o.x, 0.f); o.y = fmaxf(o.y, 0.f); }
        *reinterpret_cast<float2*>(out + (size_t)warp * N + lane * 2) = o;
    }
}

// --------------------------- launch ------------------------------------------

extern "C" void kernel_launch(void* const* d_in, const int* in_sizes, int n_in,
                              void* d_out, int out_size) {
    const float* x  = (const float*)d_in[0];
    const int*   ei = (const int*)d_in[1];          // int32 edge_index
    const float* W0 = (const float*)d_in[2];
    const float* b0 = (const float*)d_in[3];
    const float* W1 = (const float*)d_in[4];
    const float* b1 = (const float*)d_in[5];
    const float* W2 = (const float*)d_in[6];
    const float* b2 = (const float*)d_in[7];
    const float* W3 = (const float*)d_in[8];
    const float* b3 = (const float*)d_in[9];
    float* out = (float*)d_out;

    const int M = in_sizes[0] / 256;   // 50000 nodes
    const int E = in_sizes[1] / 2;     // 800000 edges
    const int T = 256;

    // ---- graph preprocessing: degrees, norms, CSR by dst (no scan)
    zero_counts_kernel<<<(M + T - 1) / T, T>>>(M);
    count_deg_kernel<<<(2 * E + T - 1) / T, T>>>(ei, E);
    norms_alloc_kernel<<<(M + T - 1) / T, T>>>(M);
    fill_csr_kernel<<<(E + T - 1) / T, T>>>(ei, E);

    const int gemm_blocks = (M + 127) / 128;
    const int agg_blocks  = (M * 32 + T - 1) / T;

    // ---- layer 0: 256 -> 128, relu
    gemm_rowscale_kernel<256, 128, false><<<gemm_blocks, 256>>>(x, W0, M);
    aggregate_kernel<128, true, false><<<agg_blocks, T>>>(b0, nullptr, M);

    // ---- layer 1: 128 -> 128, relu
    gemm_rowscale_kernel<128, 128, true><<<gemm_blocks, 256>>>(nullptr, W1, M);
    aggregate_kernel<128, true, false><<<agg_blocks, T>>>(b1, nullptr, M);

    // ---- layer 2: 128 -> 128, relu
    gemm_rowscale_kernel<128, 128, true><<<gemm_blocks, 256>>>(nullptr, W2, M);
    aggregate_kernel<128, true, false><<<agg_blocks, T>>>(b2, nullptr, M);

    // ---- layer 3: 128 -> 64, no relu, write d_out
    gemm_rowscale_kernel<128, 64, true><<<gemm_blocks, 256>>>(nullptr, W3, M);
    aggregate_kernel<64, false, true><<<agg_blocks, T>>>(b3, out, M);
}

// round 10
// speedup vs baseline: 2.0595x; 1.8522x over previous
#include <cuda_runtime.h>
#include <cuda_bf16.h>
#include <cstdint>

// ---------------------------------------------------------------------------
// GCN 4-layer. GEMMs on tensor cores via mma.sync bf16 m16n8k16 (base-target
// HMMA -- tcgen05 is unavailable: harness compiles for compute_103, not 103a)
// with bf16x3 split:  x@W ~= hi@Whi + hi@Wlo + lo@Whi  (fp32 accum).
// Aggregation: CSR gather (bump-allocated buckets, no float atomics).
// edge_index is INT32: ei[0..E)=src, ei[E..2E)=dst.
// ---------------------------------------------------------------------------

#define NN_MAX 50000
#define EE_MAX 800000
#define WT_TOTAL 73728   // 128*256 + 128*128 + 128*128 + 64*128

__device__ __align__(16) float g_h  [NN_MAX * 128]; // gemm output (messages)
__device__ __align__(16) float g_act[NN_MAX * 128]; // layer activation
__device__ float g_non[NN_MAX];
__device__ float g_nin[NN_MAX];
__device__ int   g_cout[NN_MAX];
__device__ int   g_cin [NN_MAX];
__device__ int   g_off [NN_MAX];
__device__ int   g_cur [NN_MAX];
__device__ int   g_csrc[EE_MAX];
__device__ int   g_total;
__device__ __align__(16) __nv_bfloat16 g_wt_hi[WT_TOTAL]; // Wt[N,K] bf16 hi
__device__ __align__(16) __nv_bfloat16 g_wt_lo[WT_TOTAL]; // Wt[N,K] bf16 lo

// --------------------------- helpers ----------------------------------------

__device__ __forceinline__ uint32_t smem_u32(const void* p) {
    uint32_t a;
    asm("{ .reg .u64 t; cvta.to.shared.u64 t, %1; cvt.u32.u64 %0, t; }"
        : "=r"(a) : "l"(p));
    return a;
}

__device__ __forceinline__ void ldmatrix_x4(uint32_t& r0, uint32_t& r1,
                                            uint32_t& r2, uint32_t& r3,
                                            uint32_t addr) {
    asm volatile("ldmatrix.sync.aligned.m8n8.x4.shared.b16 {%0,%1,%2,%3}, [%4];"
                 : "=r"(r0), "=r"(r1), "=r"(r2), "=r"(r3) : "r"(addr));
}

__device__ __forceinline__ void mma_bf16(float* d, const uint32_t* a, const uint32_t* b) {
    asm volatile(
        "mma.sync.aligned.m16n8k16.row.col.f32.bf16.bf16.f32 "
        "{%0,%1,%2,%3}, {%4,%5,%6,%7}, {%8,%9}, {%0,%1,%2,%3};"
        : "+f"(d[0]), "+f"(d[1]), "+f"(d[2]), "+f"(d[3])
        : "r"(a[0]), "r"(a[1]), "r"(a[2]), "r"(a[3]), "r"(b[0]), "r"(b[1]));
}

// --------------------------- preprocessing ----------------------------------

__global__ void zero_counts_kernel(int n) {
    int i = blockIdx.x * blockDim.x + threadIdx.x;
    if (i < n) { g_cout[i] = 0; g_cin[i] = 0; }
    if (i == 0) g_total = 0;
}

__global__ void count_deg_kernel(const int* __restrict__ ei, int E) {
    int i = blockIdx.x * blockDim.x + threadIdx.x;
    if (i >= 2 * E) return;
    int v = ei[i];
    if (i < E) atomicAdd(&g_cout[v], 1);
    else       atomicAdd(&g_cin[v], 1);
}

__global__ void norms_alloc_kernel(int n) {
    int i = blockIdx.x * blockDim.x + threadIdx.x;
    if (i >= n) return;
    int cin  = g_cin[i];
    int cout = g_cout[i];
    g_non[i] = rsqrtf(fmaxf((float)cout, 1.0f));
    g_nin[i] = rsqrtf(fmaxf((float)cin,  1.0f));
    int beg = atomicAdd(&g_total, cin);
    g_off[i] = beg;
    g_cur[i] = beg;
}

__global__ void fill_csr_kernel(const int* __restrict__ ei, int E) {
    int e = blockIdx.x * blockDim.x + threadIdx.x;
    if (e >= E) return;
    int s = ei[e];
    int d = ei[E + e];
    int pos = atomicAdd(&g_cur[d], 1);
    g_csrc[pos] = s;
}

// Wt_{hi,lo}[n*K + k] = split(W[k*N + n]); layers packed at fixed offsets.
__global__ void weight_prep_kernel(const float* __restrict__ W0, const float* __restrict__ W1,
                                   const float* __restrict__ W2, const float* __restrict__ W3) {
    int t = blockIdx.x * blockDim.x + threadIdx.x;
    if (t >= WT_TOTAL) return;
    const float* W; int K, N, i;
    if (t < 32768)      { W = W0; K = 256; N = 128; i = t; }
    else if (t < 49152) { W = W1; K = 128; N = 128; i = t - 32768; }
    else if (t < 65536) { W = W2; K = 128; N = 128; i = t - 49152; }
    else                { W = W3; K = 128; N = 64;  i = t - 65536; }
    int k = i % K, n = i / K;
    float v = W[k * N + n];
    __nv_bfloat16 hb = __float2bfloat16(v);
    float r = v - __bfloat162float(hb);
    g_wt_hi[t] = hb;
    g_wt_lo[t] = __float2bfloat16(r);
}

// --------------------------- tensor-core GEMM (bf16x3) ----------------------
// g_h[m][n] = g_non[m] * sum_k A[m][k] * W[k][n]
// M-tile 128 per CTA, 8 warps. smem pitch 72 bf16 (conflict-free ldmatrix/LDS).

template<int K, int N, bool A_FROM_ACT>
__global__ void __launch_bounds__(256) gemm_mma_kernel(
    const float* __restrict__ Ap, int wt_off, int M)
{
    constexpr int KT  = 64;
    constexpr int NCH = K / KT;
    constexpr int P   = 72;                 // smem pitch in bf16 elems
    constexpr int WM  = (N == 128) ? 64 : 32;
    constexpr int WN  = 32;
    constexpr int WGN = N / WN;             // warps along N: 4 or 2
    constexpr int MT  = WM / 16;            // m16 tiles per warp: 4 or 2
    constexpr int NT  = WN / 8;             // n8 tiles per warp: 4

    extern __shared__ __nv_bfloat16 sm[];
    __nv_bfloat16* sAh = sm;                   // [128][P]
    __nv_bfloat16* sAl = sAh + 128 * P;
    __nv_bfloat16* sBh = sAl + 128 * P;        // [N][P]
    __nv_bfloat16* sBl = sBh + N * P;

    const int tid  = threadIdx.x;
    const int w    = tid >> 5;
    const int lane = tid & 31;
    const int gid  = lane >> 2;   // groupID
    const int tig  = lane & 3;    // thread-in-group
    const int wm   = w / WGN, wn = w % WGN;
    const int m0   = blockIdx.x * 128;

    const float* __restrict__ A = A_FROM_ACT ? g_act : Ap;
    const __nv_bfloat16* __restrict__ wh = g_wt_hi + wt_off;
    const __nv_bfloat16* __restrict__ wl = g_wt_lo + wt_off;

    float acc[MT][NT][4];
#pragma unroll
    for (int mt = 0; mt < MT; mt++)
#pragma unroll
        for (int nt = 0; nt < NT; nt++)
#pragma unroll
            for (int j = 0; j < 4; j++) acc[mt][nt][j] = 0.0f;

    for (int ch = 0; ch < NCH; ch++) {
        const int k0g = ch * KT;
        // ---- A chunk: 128 x 64 fp32 -> hi/lo bf16 in smem
#pragma unroll
        for (int it = 0; it < 4; it++) {
            int t = tid + it * 256;          // 128*8 items
            int row = t >> 3, g8 = t & 7;
            int gm = m0 + row;
            float f[8];
            if (gm < M) {
                const float4* ap = reinterpret_cast<const float4*>(
                    A + (size_t)gm * K + k0g + g8 * 8);
                float4 f0 = ap[0], f1 = ap[1];
                f[0]=f0.x; f[1]=f0.y; f[2]=f0.z; f[3]=f0.w;
                f[4]=f1.x; f[5]=f1.y; f[6]=f1.z; f[7]=f1.w;
            } else {
#pragma unroll
                for (int j = 0; j < 8; j++) f[j] = 0.0f;
            }
            uint32_t hw[4], lw[4];
#pragma unroll
            for (int j = 0; j < 4; j++) {
                __nv_bfloat16 h0 = __float2bfloat16(f[2*j]);
                __nv_bfloat16 h1 = __float2bfloat16(f[2*j+1]);
                float r0 = f[2*j]   - __bfloat162float(h0);
                float r1 = f[2*j+1] - __bfloat162float(h1);
                __nv_bfloat16 l0 = __float2bfloat16(r0);
                __nv_bfloat16 l1 = __float2bfloat16(r1);
                hw[j] = (uint32_t)__bfloat16_as_ushort(h0) |
                        ((uint32_t)__bfloat16_as_ushort(h1) << 16);
                lw[j] = (uint32_t)__bfloat16_as_ushort(l0) |
                        ((uint32_t)__bfloat16_as_ushort(l1) << 16);
            }
            *reinterpret_cast<uint4*>(sAh + row * P + g8 * 8) =
                make_uint4(hw[0], hw[1], hw[2], hw[3]);
            *reinterpret_cast<uint4*>(sAl + row * P + g8 * 8) =
                make_uint4(lw[0], lw[1], lw[2], lw[3]);
        }
        // ---- B chunk: N x 64 bf16 hi/lo
        for (int t = tid; t < N * 8; t += 256) {
            int n = t >> 3, g8 = t & 7;
            size_t gofs = (size_t)n * K + k0g + g8 * 8;
            *reinterpret_cast<uint4*>(sBh + n * P + g8 * 8) =
                *reinterpret_cast<const uint4*>(wh + gofs);
            *reinterpret_cast<uint4*>(sBl + n * P + g8 * 8) =
                *reinterpret_cast<const uint4*>(wl + gofs);
        }
        __syncthreads();

#pragma unroll
        for (int ks = 0; ks < 4; ks++) {
            const int k0 = ks * 16;
            // A fragments via ldmatrix.x4: lanes 0-15 rows, 16-31 rows @ k+8
            uint32_t ah[MT][4], al[MT][4];
#pragma unroll
            for (int mt = 0; mt < MT; mt++) {
                int row = wm * WM + mt * 16 + (lane & 15);
                int kk  = k0 + (lane >> 4) * 8;
                ldmatrix_x4(ah[mt][0], ah[mt][1], ah[mt][2], ah[mt][3],
                            smem_u32(sAh + row * P + kk));
                ldmatrix_x4(al[mt][0], al[mt][1], al[mt][2], al[mt][3],
                            smem_u32(sAl + row * P + kk));
            }
            // B fragments: b0 = Wt[n][k0+tig*2..+1], b1 = +8  (col-major B)
            uint32_t bh[NT][2], bl[NT][2];
#pragma unroll
            for (int nt = 0; nt < NT; nt++) {
                int n = wn * WN + nt * 8 + gid;
                const __nv_bfloat16* ph = sBh + n * P + k0 + tig * 2;
                const __nv_bfloat16* pl = sBl + n * P + k0 + tig * 2;
                bh[nt][0] = *reinterpret_cast<const uint32_t*>(ph);
                bh[nt][1] = *reinterpret_cast<const uint32_t*>(ph + 8);
                bl[nt][0] = *reinterpret_cast<const uint32_t*>(pl);
                bl[nt][1] = *reinterpret_cast<const uint32_t*>(pl + 8);
            }
#pragma unroll
            for (int mt = 0; mt < MT; mt++)
#pragma unroll
                for (int nt = 0; nt < NT; nt++) {
                    mma_bf16(acc[mt][nt], ah[mt], bh[nt]);
                    mma_bf16(acc[mt][nt], ah[mt], bl[nt]);
                    mma_bf16(acc[mt][nt], al[mt], bh[nt]);
                }
        }
        __syncthreads();
    }

    // ---- epilogue: scale rows by g_non, store fp32
#pragma unroll
    for (int mt = 0; mt < MT; mt++) {
        int r0 = m0 + wm * WM + mt * 16 + gid;
        int r1 = r0 + 8;
        float s0 = (r0 < M) ? g_non[r0] : 0.0f;
        float s1 = (r1 < M) ? g_non[r1] : 0.0f;
#pragma unroll
        for (int nt = 0; nt < NT; nt++) {
            int n = wn * WN + nt * 8 + tig * 2;
            if (r0 < M) {
                float2 o; o.x = acc[mt][nt][0] * s0; o.y = acc[mt][nt][1] * s0;
                *reinterpret_cast<float2*>(g_h + (size_t)r0 * N + n) = o;
            }
            if (r1 < M) {
                float2 o; o.x = acc[mt][nt][2] * s1; o.y = acc[mt][nt][3] * s1;
                *reinterpret_cast<float2*>(g_h + (size_t)r1 * N + n) = o;
            }
        }
    }
}

// --------------------------- gather-aggregate --------------------------------

template<int N, bool RELU, bool TO_PARAM>
__global__ void aggregate_kernel(const float* __restrict__ bias,
                                 float* __restrict__ outp, int M) {
    constexpr int VPL = N / 32;
    int warp = (blockIdx.x * blockDim.x + threadIdx.x) >> 5;
    if (warp >= M) return;
    int lane = threadIdx.x & 31;

    int beg = g_off[warp];
    int end = beg + g_cin[warp];

    float acc[VPL];
#pragma unroll
    for (int c = 0; c < VPL; c++) acc[c] = 0.0f;

    int e = beg;
    for (; e + 1 < end; e += 2) {
        int s0 = g_csrc[e];
        int s1 = g_csrc[e + 1];
        if (VPL == 4) {
            float4 v0 = *reinterpret_cast<const float4*>(g_h + (size_t)s0 * N + lane * 4);
            float4 v1 = *reinterpret_cast<const float4*>(g_h + (size_t)s1 * N + lane * 4);
            acc[0] += v0.x + v1.x; acc[1] += v0.y + v1.y;
            acc[2] += v0.z + v1.z; acc[3] += v0.w + v1.w;
        } else {
            float2 v0 = *reinterpret_cast<const float2*>(g_h + (size_t)s0 * N + lane * 2);
            float2 v1 = *reinterpret_cast<const float2*>(g_h + (size_t)s1 * N + lane * 2);
            acc[0] += v0.x + v1.x; acc[1] += v0.y + v1.y;
        }
    }
    if (e < end) {
        int s0 = g_csrc[e];
        if (VPL == 4) {
            float4 v0 = *reinterpret_cast<const float4*>(g_h + (size_t)s0 * N + lane * 4);
            acc[0] += v0.x; acc[1] += v0.y; acc[2] += v0.z; acc[3] += v0.w;
        } else {
            float2 v0 = *reinterpret_cast<const float2*>(g_h + (size_t)s0 * N + lane * 2);
            acc[0] += v0.x; acc[1] += v0.y;
        }
    }

    float s = g_nin[warp];
    float* out = TO_PARAM ? outp : g_act;
    if (VPL == 4) {
        float4 b = reinterpret_cast<const float4*>(bias)[lane];
        float4 o;
        o.x = acc[0] * s + b.x; o.y = acc[1] * s + b.y;
        o.z = acc[2] * s + b.z; o.w = acc[3] * s + b.w;
        if (RELU) {
            o.x = fmaxf(o.x, 0.f); o.y = fmaxf(o.y, 0.f);
            o.z = fmaxf(o.z, 0.f); o.w = fmaxf(o.w, 0.f);
        }
        *reinterpret_cast<float4*>(out + (size_t)warp * N + lane * 4) = o;
    } else {
        float2 b = reinterpret_cast<const float2*>(bias)[lane];
        float2 o;
        o.x = acc[0] * s + b.x; o.y = acc[1] * s + b.y;
        if (RELU) { o.x = fmaxf(o.x, 0.f); o.y = fmaxf(o.y, 0.f); }
        *reinterpret_cast<float2*>(out + (size_t)warp * N + lane * 2) = o;
    }
}

// --------------------------- launch ------------------------------------------

extern "C" void kernel_launch(void* const* d_in, const int* in_sizes, int n_in,
                              void* d_out, int out_size) {
    const float* x  = (const float*)d_in[0];
    const int*   ei = (const int*)d_in[1];
    const float* W0 = (const float*)d_in[2];
    const float* b0 = (const float*)d_in[3];
    const float* W1 = (const float*)d_in[4];
    const float* b1 = (const float*)d_in[5];
    const float* W2 = (const float*)d_in[6];
    const float* b2 = (const float*)d_in[7];
    const float* W3 = (const float*)d_in[8];
    const float* b3 = (const float*)d_in[9];
    float* out = (float*)d_out;

    const int M = in_sizes[0] / 256;   // 50000
    const int E = in_sizes[1] / 2;     // 800000
    const int T = 256;

    // dyn smem: (128 + N) rows x 72 bf16 x 2 (hi/lo)
    const int dyn128 = (128 + 128) * 72 * 2 * 2;   // 73728
    const int dyn64  = (128 + 64)  * 72 * 2 * 2;   // 55296
    cudaFuncSetAttribute(gemm_mma_kernel<256, 128, false>,
                         cudaFuncAttributeMaxDynamicSharedMemorySize, dyn128);
    cudaFuncSetAttribute(gemm_mma_kernel<128, 128, true>,
                         cudaFuncAttributeMaxDynamicSharedMemorySize, dyn128);
    cudaFuncSetAttribute(gemm_mma_kernel<128, 64, true>,
                         cudaFuncAttributeMaxDynamicSharedMemorySize, dyn64);

    // ---- preprocessing
    zero_counts_kernel<<<(M + T - 1) / T, T>>>(M);
    count_deg_kernel<<<(2 * E + T - 1) / T, T>>>(ei, E);
    norms_alloc_kernel<<<(M + T - 1) / T, T>>>(M);
    fill_csr_kernel<<<(E + T - 1) / T, T>>>(ei, E);
    weight_prep_kernel<<<(WT_TOTAL + T - 1) / T, T>>>(W0, W1, W2, W3);

    const int gemm_blocks = (M + 127) / 128;   // 391
    const int agg_blocks  = (M * 32 + T - 1) / T;

    // ---- layer 0: 256 -> 128, relu
    gemm_mma_kernel<256, 128, false><<<gemm_blocks, 256, dyn128>>>(x, 0, M);
    aggregate_kernel<128, true, false><<<agg_blocks, T>>>(b0, nullptr, M);

    // ---- layer 1: 128 -> 128, relu
    gemm_mma_kernel<128, 128, true><<<gemm_blocks, 256, dyn128>>>(nullptr, 32768, M);
    aggregate_kernel<128, true, false><<<agg_blocks, T>>>(b1, nullptr, M);

    // ---- layer 2: 128 -> 128, relu
    gemm_mma_kernel<128, 128, true><<<gemm_blocks, 256, dyn128>>>(nullptr, 49152, M);
    aggregate_kernel<128, true, false><<<agg_blocks, T>>>(b2, nullptr, M);

    // ---- layer 3: 128 -> 64, no relu, write d_out
    gemm_mma_kernel<128, 64, true><<<gemm_blocks, 256, dyn64>>>(nullptr, 65536, M);
    aggregate_kernel<64, false, true><<<agg_blocks, T>>>(b3, out, M);
}

// round 11
// speedup vs baseline: 2.2077x; 1.0719x over previous
#include <cuda_runtime.h>
#include <cuda_bf16.h>
#include <cuda_fp16.h>
#include <cstdint>

// ---------------------------------------------------------------------------
// GCN 4-layer. GEMMs: mma.sync bf16 m16n8k16 HMMA with bf16x3 split
//   (x@W ~= hi@Whi + hi@Wlo + lo@Whi, fp32 accum).
// Messages g_h stored FP16 (halves L2 traffic of the gather, which is
// LTS-cap bound). Activations stay fp32. CSR gather, no float atomics.
// edge_index is INT32: ei[0..E)=src, ei[E..2E)=dst.
// ---------------------------------------------------------------------------

#define NN_MAX 50000
#define EE_MAX 800000
#define WT_TOTAL 73728   // 128*256 + 128*128 + 128*128 + 64*128

__device__ __align__(16) __half g_h [NN_MAX * 128]; // fp16 messages
__device__ __align__(16) float g_act[NN_MAX * 128]; // layer activation (fp32)
__device__ float g_non[NN_MAX];
__device__ float g_nin[NN_MAX];
__device__ int   g_cout[NN_MAX];
__device__ int   g_cin [NN_MAX];
__device__ int   g_off [NN_MAX];
__device__ int   g_cur [NN_MAX];
__device__ int   g_csrc[EE_MAX];
__device__ int   g_total;
__device__ __align__(16) __nv_bfloat16 g_wt_hi[WT_TOTAL]; // Wt[N,K] bf16 hi
__device__ __align__(16) __nv_bfloat16 g_wt_lo[WT_TOTAL]; // Wt[N,K] bf16 lo

// --------------------------- helpers ----------------------------------------

__device__ __forceinline__ uint32_t smem_u32(const void* p) {
    uint32_t a;
    asm("{ .reg .u64 t; cvta.to.shared.u64 t, %1; cvt.u32.u64 %0, t; }"
        : "=r"(a) : "l"(p));
    return a;
}

__device__ __forceinline__ void ldmatrix_x4(uint32_t& r0, uint32_t& r1,
                                            uint32_t& r2, uint32_t& r3,
                                            uint32_t addr) {
    asm volatile("ldmatrix.sync.aligned.m8n8.x4.shared.b16 {%0,%1,%2,%3}, [%4];"
                 : "=r"(r0), "=r"(r1), "=r"(r2), "=r"(r3) : "r"(addr));
}

__device__ __forceinline__ void mma_bf16(float* d, const uint32_t* a, const uint32_t* b) {
    asm volatile(
        "mma.sync.aligned.m16n8k16.row.col.f32.bf16.bf16.f32 "
        "{%0,%1,%2,%3}, {%4,%5,%6,%7}, {%8,%9}, {%0,%1,%2,%3};"
        : "+f"(d[0]), "+f"(d[1]), "+f"(d[2]), "+f"(d[3])
        : "r"(a[0]), "r"(a[1]), "r"(a[2]), "r"(a[3]), "r"(b[0]), "r"(b[1]));
}

// --------------------------- preprocessing ----------------------------------

__global__ void zero_counts_kernel(int n) {
    int i = blockIdx.x * blockDim.x + threadIdx.x;
    if (i < n) { g_cout[i] = 0; g_cin[i] = 0; }
    if (i == 0) g_total = 0;
}

__global__ void count_deg_kernel(const int* __restrict__ ei, int E) {
    int i = blockIdx.x * blockDim.x + threadIdx.x;
    if (i >= 2 * E) return;
    int v = ei[i];
    if (i < E) atomicAdd(&g_cout[v], 1);
    else       atomicAdd(&g_cin[v], 1);
}

__global__ void norms_alloc_kernel(int n) {
    int i = blockIdx.x * blockDim.x + threadIdx.x;
    if (i >= n) return;
    int cin  = g_cin[i];
    int cout = g_cout[i];
    g_non[i] = rsqrtf(fmaxf((float)cout, 1.0f));
    g_nin[i] = rsqrtf(fmaxf((float)cin,  1.0f));
    int beg = atomicAdd(&g_total, cin);
    g_off[i] = beg;
    g_cur[i] = beg;
}

__global__ void fill_csr_kernel(const int* __restrict__ ei, int E) {
    int e = blockIdx.x * blockDim.x + threadIdx.x;
    if (e >= E) return;
    int s = ei[e];
    int d = ei[E + e];
    int pos = atomicAdd(&g_cur[d], 1);
    g_csrc[pos] = s;
}

// Wt_{hi,lo}[n*K + k] = split(W[k*N + n]); layers packed at fixed offsets.
__global__ void weight_prep_kernel(const float* __restrict__ W0, const float* __restrict__ W1,
                                   const float* __restrict__ W2, const float* __restrict__ W3) {
    int t = blockIdx.x * blockDim.x + threadIdx.x;
    if (t >= WT_TOTAL) return;
    const float* W; int K, N, i;
    if (t < 32768)      { W = W0; K = 256; N = 128; i = t; }
    else if (t < 49152) { W = W1; K = 128; N = 128; i = t - 32768; }
    else if (t < 65536) { W = W2; K = 128; N = 128; i = t - 49152; }
    else                { W = W3; K = 128; N = 64;  i = t - 65536; }
    int k = i % K, n = i / K;
    float v = W[k * N + n];
    __nv_bfloat16 hb = __float2bfloat16(v);
    float r = v - __bfloat162float(hb);
    g_wt_hi[t] = hb;
    g_wt_lo[t] = __float2bfloat16(r);
}

// --------------------------- tensor-core GEMM (bf16x3) ----------------------
// g_h[m][n] = fp16( g_non[m] * sum_k A[m][k] * W[k][n] )

template<int K, int N, bool A_FROM_ACT>
__global__ void __launch_bounds__(256) gemm_mma_kernel(
    const float* __restrict__ Ap, int wt_off, int M)
{
    constexpr int KT  = 64;
    constexpr int NCH = K / KT;
    constexpr int P   = 72;                 // smem pitch in bf16 elems
    constexpr int WM  = (N == 128) ? 64 : 32;
    constexpr int WN  = 32;
    constexpr int WGN = N / WN;             // warps along N: 4 or 2
    constexpr int MT  = WM / 16;            // m16 tiles per warp
    constexpr int NT  = WN / 8;             // n8 tiles per warp

    extern __shared__ __nv_bfloat16 sm[];
    __nv_bfloat16* sAh = sm;                   // [128][P]
    __nv_bfloat16* sAl = sAh + 128 * P;
    __nv_bfloat16* sBh = sAl + 128 * P;        // [N][P]
    __nv_bfloat16* sBl = sBh + N * P;

    const int tid  = threadIdx.x;
    const int w    = tid >> 5;
    const int lane = tid & 31;
    const int gid  = lane >> 2;
    const int tig  = lane & 3;
    const int wm   = w / WGN, wn = w % WGN;
    const int m0   = blockIdx.x * 128;

    const float* __restrict__ A = A_FROM_ACT ? g_act : Ap;
    const __nv_bfloat16* __restrict__ wh = g_wt_hi + wt_off;
    const __nv_bfloat16* __restrict__ wl = g_wt_lo + wt_off;

    float acc[MT][NT][4];
#pragma unroll
    for (int mt = 0; mt < MT; mt++)
#pragma unroll
        for (int nt = 0; nt < NT; nt++)
#pragma unroll
            for (int j = 0; j < 4; j++) acc[mt][nt][j] = 0.0f;

    for (int ch = 0; ch < NCH; ch++) {
        const int k0g = ch * KT;
        // ---- A chunk: 128 x 64 fp32 -> hi/lo bf16 in smem
#pragma unroll
        for (int it = 0; it < 4; it++) {
            int t = tid + it * 256;          // 128*8 items
            int row = t >> 3, g8 = t & 7;
            int gm = m0 + row;
            float f[8];
            if (gm < M) {
                const float4* ap = reinterpret_cast<const float4*>(
                    A + (size_t)gm * K + k0g + g8 * 8);
                float4 f0 = ap[0], f1 = ap[1];
                f[0]=f0.x; f[1]=f0.y; f[2]=f0.z; f[3]=f0.w;
                f[4]=f1.x; f[5]=f1.y; f[6]=f1.z; f[7]=f1.w;
            } else {
#pragma unroll
                for (int j = 0; j < 8; j++) f[j] = 0.0f;
            }
            uint32_t hw[4], lw[4];
#pragma unroll
            for (int j = 0; j < 4; j++) {
                __nv_bfloat16 h0 = __float2bfloat16(f[2*j]);
                __nv_bfloat16 h1 = __float2bfloat16(f[2*j+1]);
                float r0 = f[2*j]   - __bfloat162float(h0);
                float r1 = f[2*j+1] - __bfloat162float(h1);
                __nv_bfloat16 l0 = __float2bfloat16(r0);
                __nv_bfloat16 l1 = __float2bfloat16(r1);
                hw[j] = (uint32_t)__bfloat16_as_ushort(h0) |
                        ((uint32_t)__bfloat16_as_ushort(h1) << 16);
                lw[j] = (uint32_t)__bfloat16_as_ushort(l0) |
                        ((uint32_t)__bfloat16_as_ushort(l1) << 16);
            }
            *reinterpret_cast<uint4*>(sAh + row * P + g8 * 8) =
                make_uint4(hw[0], hw[1], hw[2], hw[3]);
            *reinterpret_cast<uint4*>(sAl + row * P + g8 * 8) =
                make_uint4(lw[0], lw[1], lw[2], lw[3]);
        }
        // ---- B chunk: N x 64 bf16 hi/lo
        for (int t = tid; t < N * 8; t += 256) {
            int n = t >> 3, g8 = t & 7;
            size_t gofs = (size_t)n * K + k0g + g8 * 8;
            *reinterpret_cast<uint4*>(sBh + n * P + g8 * 8) =
                *reinterpret_cast<const uint4*>(wh + gofs);
            *reinterpret_cast<uint4*>(sBl + n * P + g8 * 8) =
                *reinterpret_cast<const uint4*>(wl + gofs);
        }
        __syncthreads();

#pragma unroll
        for (int ks = 0; ks < 4; ks++) {
            const int k0 = ks * 16;
            uint32_t ah[MT][4], al[MT][4];
#pragma unroll
            for (int mt = 0; mt < MT; mt++) {
                int row = wm * WM + mt * 16 + (lane & 15);
                int kk  = k0 + (lane >> 4) * 8;
                ldmatrix_x4(ah[mt][0], ah[mt][1], ah[mt][2], ah[mt][3],
                            smem_u32(sAh + row * P + kk));
                ldmatrix_x4(al[mt][0], al[mt][1], al[mt][2], al[mt][3],
                            smem_u32(sAl + row * P + kk));
            }
            uint32_t bh[NT][2], bl[NT][2];
#pragma unroll
            for (int nt = 0; nt < NT; nt++) {
                int n = wn * WN + nt * 8 + gid;
                const __nv_bfloat16* ph = sBh + n * P + k0 + tig * 2;
                const __nv_bfloat16* pl = sBl + n * P + k0 + tig * 2;
                bh[nt][0] = *reinterpret_cast<const uint32_t*>(ph);
                bh[nt][1] = *reinterpret_cast<const uint32_t*>(ph + 8);
                bl[nt][0] = *reinterpret_cast<const uint32_t*>(pl);
                bl[nt][1] = *reinterpret_cast<const uint32_t*>(pl + 8);
            }
#pragma unroll
            for (int mt = 0; mt < MT; mt++)
#pragma unroll
                for (int nt = 0; nt < NT; nt++) {
                    mma_bf16(acc[mt][nt], ah[mt], bh[nt]);
                    mma_bf16(acc[mt][nt], ah[mt], bl[nt]);
                    mma_bf16(acc[mt][nt], al[mt], bh[nt]);
                }
        }
        __syncthreads();
    }

    // ---- epilogue: scale rows by g_non, store fp16
#pragma unroll
    for (int mt = 0; mt < MT; mt++) {
        int r0 = m0 + wm * WM + mt * 16 + gid;
        int r1 = r0 + 8;
        float s0 = (r0 < M) ? g_non[r0] : 0.0f;
        float s1 = (r1 < M) ? g_non[r1] : 0.0f;
#pragma unroll
        for (int nt = 0; nt < NT; nt++) {
            int n = wn * WN + nt * 8 + tig * 2;
            if (r0 < M) {
                __half2 o = __floats2half2_rn(acc[mt][nt][0] * s0, acc[mt][nt][1] * s0);
                *reinterpret_cast<__half2*>(g_h + (size_t)r0 * N + n) = o;
            }
            if (r1 < M) {
                __half2 o = __floats2half2_rn(acc[mt][nt][2] * s1, acc[mt][nt][3] * s1);
                *reinterpret_cast<__half2*>(g_h + (size_t)r1 * N + n) = o;
            }
        }
    }
}

// --------------------------- gather-aggregate --------------------------------
// One warp per dst node; lane owns N/32 halfs; fp32 accumulation.

template<int N, bool RELU, bool TO_PARAM>
__global__ void aggregate_kernel(const float* __restrict__ bias,
                                 float* __restrict__ outp, int M) {
    constexpr int VPL = N / 32;   // halfs per lane: 4 (N=128) or 2 (N=64)
    int warp = (blockIdx.x * blockDim.x + threadIdx.x) >> 5;
    if (warp >= M) return;
    int lane = threadIdx.x & 31;

    int beg = g_off[warp];
    int end = beg + g_cin[warp];

    float acc[VPL];
#pragma unroll
    for (int c = 0; c < VPL; c++) acc[c] = 0.0f;

    int e = beg;
    for (; e + 1 < end; e += 2) {   // unroll-by-2 for MLP
        int s0 = g_csrc[e];
        int s1 = g_csrc[e + 1];
        if (VPL == 4) {
            uint2 u0 = *reinterpret_cast<const uint2*>(g_h + (size_t)s0 * N + lane * 4);
            uint2 u1 = *reinterpret_cast<const uint2*>(g_h + (size_t)s1 * N + lane * 4);
            float2 a0 = __half22float2(*reinterpret_cast<__half2*>(&u0.x));
            float2 a1 = __half22float2(*reinterpret_cast<__half2*>(&u0.y));
            float2 c0 = __half22float2(*reinterpret_cast<__half2*>(&u1.x));
            float2 c1 = __half22float2(*reinterpret_cast<__half2*>(&u1.y));
            acc[0] += a0.x + c0.x; acc[1] += a0.y + c0.y;
            acc[2] += a1.x + c1.x; acc[3] += a1.y + c1.y;
        } else {
            uint32_t u0 = *reinterpret_cast<const uint32_t*>(g_h + (size_t)s0 * N + lane * 2);
            uint32_t u1 = *reinterpret_cast<const uint32_t*>(g_h + (size_t)s1 * N + lane * 2);
            float2 a0 = __half22float2(*reinterpret_cast<__half2*>(&u0));
            float2 c0 = __half22float2(*reinterpret_cast<__half2*>(&u1));
            acc[0] += a0.x + c0.x; acc[1] += a0.y + c0.y;
        }
    }
    if (e < end) {
        int s0 = g_csrc[e];
        if (VPL == 4) {
            uint2 u0 = *reinterpret_cast<const uint2*>(g_h + (size_t)s0 * N + lane * 4);
            float2 a0 = __half22float2(*reinterpret_cast<__half2*>(&u0.x));
            float2 a1 = __half22float2(*reinterpret_cast<__half2*>(&u0.y));
            acc[0] += a0.x; acc[1] += a0.y; acc[2] += a1.x; acc[3] += a1.y;
        } else {
            uint32_t u0 = *reinterpret_cast<const uint32_t*>(g_h + (size_t)s0 * N + lane * 2);
            float2 a0 = __half22float2(*reinterpret_cast<__half2*>(&u0));
            acc[0] += a0.x; acc[1] += a0.y;
        }
    }

    float s = g_nin[warp];
    float* out = TO_PARAM ? outp : g_act;
    if (VPL == 4) {
        float4 b = reinterpret_cast<const float4*>(bias)[lane];
        float4 o;
        o.x = acc[0] * s + b.x; o.y = acc[1] * s + b.y;
        o.z = acc[2] * s + b.z; o.w = acc[3] * s + b.w;
        if (RELU) {
            o.x = fmaxf(o.x, 0.f); o.y = fmaxf(o.y, 0.f);
            o.z = fmaxf(o.z, 0.f); o.w = fmaxf(o.w, 0.f);
        }
        *reinterpret_cast<float4*>(out + (size_t)warp * N + lane * 4) = o;
    } else {
        float2 b = reinterpret_cast<const float2*>(bias)[lane];
        float2 o;
        o.x = acc[0] * s + b.x; o.y = acc[1] * s + b.y;
        if (RELU) { o.x = fmaxf(o.x, 0.f); o.y = fmaxf(o.y, 0.f); }
        *reinterpret_cast<float2*>(out + (size_t)warp * N + lane * 2) = o;
    }
}

// --------------------------- launch ------------------------------------------

extern "C" void kernel_launch(void* const* d_in, const int* in_sizes, int n_in,
                              void* d_out, int out_size) {
    const float* x  = (const float*)d_in[0];
    const int*   ei = (const int*)d_in[1];
    const float* W0 = (const float*)d_in[2];
    const float* b0 = (const float*)d_in[3];
    const float* W1 = (const float*)d_in[4];
    const float* b1 = (const float*)d_in[5];
    const float* W2 = (const float*)d_in[6];
    const float* b2 = (const float*)d_in[7];
    const float* W3 = (const float*)d_in[8];
    const float* b3 = (const float*)d_in[9];
    float* out = (float*)d_out;

    const int M = in_sizes[0] / 256;   // 50000
    const int E = in_sizes[1] / 2;     // 800000
    const int T = 256;

    const int dyn128 = (128 + 128) * 72 * 2 * 2;   // 73728
    const int dyn64  = (128 + 64)  * 72 * 2 * 2;   // 55296
    cudaFuncSetAttribute(gemm_mma_kernel<256, 128, false>,
                         cudaFuncAttributeMaxDynamicSharedMemorySize, dyn128);
    cudaFuncSetAttribute(gemm_mma_kernel<128, 128, true>,
                         cudaFuncAttributeMaxDynamicSharedMemorySize, dyn128);
    cudaFuncSetAttribute(gemm_mma_kernel<128, 64, true>,
                         cudaFuncAttributeMaxDynamicSharedMemorySize, dyn64);

    // ---- preprocessing
    zero_counts_kernel<<<(M + T - 1) / T, T>>>(M);
    count_deg_kernel<<<(2 * E + T - 1) / T, T>>>(ei, E);
    norms_alloc_kernel<<<(M + T - 1) / T, T>>>(M);
    fill_csr_kernel<<<(E + T - 1) / T, T>>>(ei, E);
    weight_prep_kernel<<<(WT_TOTAL + T - 1) / T, T>>>(W0, W1, W2, W3);

    const int gemm_blocks = (M + 127) / 128;   // 391
    const int agg_blocks  = (M * 32 + T - 1) / T;

    // ---- layer 0: 256 -> 128, relu
    gemm_mma_kernel<256, 128, false><<<gemm_blocks, 256, dyn128>>>(x, 0, M);
    aggregate_kernel<128, true, false><<<agg_blocks, T>>>(b0, nullptr, M);

    // ---- layer 1: 128 -> 128, relu
    gemm_mma_kernel<128, 128, true><<<gemm_blocks, 256, dyn128>>>(nullptr, 32768, M);
    aggregate_kernel<128, true, false><<<agg_blocks, T>>>(b1, nullptr, M);

    // ---- layer 2: 128 -> 128, relu
    gemm_mma_kernel<128, 128, true><<<gemm_blocks, 256, dyn128>>>(nullptr, 49152, M);
    aggregate_kernel<128, true, false><<<agg_blocks, T>>>(b2, nullptr, M);

    // ---- layer 3: 128 -> 64, no relu, write d_out
    gemm_mma_kernel<128, 64, true><<<gemm_blocks, 256, dyn64>>>(nullptr, 65536, M);
    aggregate_kernel<64, false, true><<<agg_blocks, T>>>(b3, out, M);
}

// round 12
// speedup vs baseline: 2.2448x; 1.0168x over previous
#include <cuda_runtime.h>
#include <cuda_bf16.h>
#include <cuda_fp16.h>
#include <cstdint>

// ---------------------------------------------------------------------------
// GCN 4-layer. GEMMs: mma.sync bf16 m16n8k16 HMMA, bf16x3 split
//   (x@W ~= hi@Whi + hi@Wlo + lo@Whi, fp32 accum).
// Activations stored PRE-SPLIT as bf16 hi/lo (split in aggregate epilogue),
// so hidden-layer GEMMs load ready bf16. Messages g_h stored FP16.
// CSR gather with MLP=4 unroll. edge_index INT32: ei[0..E)=src, ei[E..2E)=dst.
// ---------------------------------------------------------------------------

#define NN_MAX 50000
#define EE_MAX 800000
#define WT_TOTAL 73728   // 128*256 + 128*128 + 128*128 + 64*128

__device__ __align__(16) __half g_h [NN_MAX * 128];          // fp16 messages
__device__ __align__(16) __nv_bfloat16 g_act_hi[NN_MAX * 128]; // act hi
__device__ __align__(16) __nv_bfloat16 g_act_lo[NN_MAX * 128]; // act lo
__device__ float g_non[NN_MAX];
__device__ float g_nin[NN_MAX];
__device__ int   g_cout[NN_MAX];
__device__ int   g_cin [NN_MAX];
__device__ int   g_off [NN_MAX];
__device__ int   g_cur [NN_MAX];
__device__ int   g_csrc[EE_MAX];
__device__ int   g_total;
__device__ __align__(16) __nv_bfloat16 g_wt_hi[WT_TOTAL]; // Wt[N,K] bf16 hi
__device__ __align__(16) __nv_bfloat16 g_wt_lo[WT_TOTAL]; // Wt[N,K] bf16 lo

// --------------------------- helpers ----------------------------------------

__device__ __forceinline__ uint32_t smem_u32(const void* p) {
    uint32_t a;
    asm("{ .reg .u64 t; cvta.to.shared.u64 t, %1; cvt.u32.u64 %0, t; }"
        : "=r"(a) : "l"(p));
    return a;
}

__device__ __forceinline__ void ldmatrix_x4(uint32_t& r0, uint32_t& r1,
                                            uint32_t& r2, uint32_t& r3,
                                            uint32_t addr) {
    asm volatile("ldmatrix.sync.aligned.m8n8.x4.shared.b16 {%0,%1,%2,%3}, [%4];"
                 : "=r"(r0), "=r"(r1), "=r"(r2), "=r"(r3) : "r"(addr));
}

__device__ __forceinline__ void mma_bf16(float* d, const uint32_t* a, const uint32_t* b) {
    asm volatile(
        "mma.sync.aligned.m16n8k16.row.col.f32.bf16.bf16.f32 "
        "{%0,%1,%2,%3}, {%4,%5,%6,%7}, {%8,%9}, {%0,%1,%2,%3};"
        : "+f"(d[0]), "+f"(d[1]), "+f"(d[2]), "+f"(d[3])
        : "r"(a[0]), "r"(a[1]), "r"(a[2]), "r"(a[3]), "r"(b[0]), "r"(b[1]));
}

__device__ __forceinline__ uint32_t pack_bf16(float a, float b) {
    __nv_bfloat162 t = __floats2bfloat162_rn(a, b);
    return *reinterpret_cast<uint32_t*>(&t);
}

// --------------------------- preprocessing ----------------------------------

__global__ void zero_counts_kernel(int n) {
    int i = blockIdx.x * blockDim.x + threadIdx.x;
    if (i < n) { g_cout[i] = 0; g_cin[i] = 0; }
    if (i == 0) g_total = 0;
}

__global__ void count_deg_kernel(const int* __restrict__ ei, int E) {
    int i = blockIdx.x * blockDim.x + threadIdx.x;
    if (i >= 2 * E) return;
    int v = ei[i];
    if (i < E) atomicAdd(&g_cout[v], 1);
    else       atomicAdd(&g_cin[v], 1);
}

__global__ void norms_alloc_kernel(int n) {
    int i = blockIdx.x * blockDim.x + threadIdx.x;
    if (i >= n) return;
    int cin  = g_cin[i];
    int cout = g_cout[i];
    g_non[i] = rsqrtf(fmaxf((float)cout, 1.0f));
    g_nin[i] = rsqrtf(fmaxf((float)cin,  1.0f));
    int beg = atomicAdd(&g_total, cin);
    g_off[i] = beg;
    g_cur[i] = beg;
}

__global__ void fill_csr_kernel(const int* __restrict__ ei, int E) {
    int e = blockIdx.x * blockDim.x + threadIdx.x;
    if (e >= E) return;
    int s = ei[e];
    int d = ei[E + e];
    int pos = atomicAdd(&g_cur[d], 1);
    g_csrc[pos] = s;
}

// Wt_{hi,lo}[n*K + k] = split(W[k*N + n]); layers packed at fixed offsets.
__global__ void weight_prep_kernel(const float* __restrict__ W0, const float* __restrict__ W1,
                                   const float* __restrict__ W2, const float* __restrict__ W3) {
    int t = blockIdx.x * blockDim.x + threadIdx.x;
    if (t >= WT_TOTAL) return;
    const float* W; int K, N, i;
    if (t < 32768)      { W = W0; K = 256; N = 128; i = t; }
    else if (t < 49152) { W = W1; K = 128; N = 128; i = t - 32768; }
    else if (t < 65536) { W = W2; K = 128; N = 128; i = t - 49152; }
    else                { W = W3; K = 128; N = 64;  i = t - 65536; }
    int k = i % K, n = i / K;
    float v = W[k * N + n];
    __nv_bfloat16 hb = __float2bfloat16(v);
    float r = v - __bfloat162float(hb);
    g_wt_hi[t] = hb;
    g_wt_lo[t] = __float2bfloat16(r);
}

// --------------------------- tensor-core GEMM (bf16x3) ----------------------
// g_h[m][n] = fp16( g_non[m] * sum_k A[m][k] * W[k][n] )
// A_FROM_ACT: A comes pre-split from g_act_hi/g_act_lo (bf16 direct copy).

template<int K, int N, bool A_FROM_ACT>
__global__ void __launch_bounds__(256) gemm_mma_kernel(
    const float* __restrict__ Ap, int wt_off, int M)
{
    constexpr int KT  = 64;
    constexpr int NCH = K / KT;
    constexpr int P   = 72;                 // smem pitch in bf16 elems
    constexpr int WM  = (N == 128) ? 64 : 32;
    constexpr int WN  = 32;
    constexpr int WGN = N / WN;
    constexpr int MT  = WM / 16;
    constexpr int NT  = WN / 8;

    extern __shared__ __nv_bfloat16 sm[];
    __nv_bfloat16* sAh = sm;                   // [128][P]
    __nv_bfloat16* sAl = sAh + 128 * P;
    __nv_bfloat16* sBh = sAl + 128 * P;        // [N][P]
    __nv_bfloat16* sBl = sBh + N * P;

    const int tid  = threadIdx.x;
    const int w    = tid >> 5;
    const int lane = tid & 31;
    const int gid  = lane >> 2;
    const int tig  = lane & 3;
    const int wm   = w / WGN, wn = w % WGN;
    const int m0   = blockIdx.x * 128;

    const __nv_bfloat16* __restrict__ wh = g_wt_hi + wt_off;
    const __nv_bfloat16* __restrict__ wl = g_wt_lo + wt_off;

    float acc[MT][NT][4];
#pragma unroll
    for (int mt = 0; mt < MT; mt++)
#pragma unroll
        for (int nt = 0; nt < NT; nt++)
#pragma unroll
            for (int j = 0; j < 4; j++) acc[mt][nt][j] = 0.0f;

    for (int ch = 0; ch < NCH; ch++) {
        const int k0g = ch * KT;
        // ---- A chunk: 128 rows x 64
#pragma unroll
        for (int it = 0; it < 4; it++) {
            int t = tid + it * 256;          // 128*8 items
            int row = t >> 3, g8 = t & 7;
            int gm = m0 + row;
            if (A_FROM_ACT) {
                uint4 hv = make_uint4(0,0,0,0), lv = make_uint4(0,0,0,0);
                if (gm < M) {
                    size_t gofs = (size_t)gm * K + k0g + g8 * 8;
                    hv = *reinterpret_cast<const uint4*>(g_act_hi + gofs);
                    lv = *reinterpret_cast<const uint4*>(g_act_lo + gofs);
                }
                *reinterpret_cast<uint4*>(sAh + row * P + g8 * 8) = hv;
                *reinterpret_cast<uint4*>(sAl + row * P + g8 * 8) = lv;
            } else {
                float f[8];
                if (gm < M) {
                    const float4* ap = reinterpret_cast<const float4*>(
                        Ap + (size_t)gm * K + k0g + g8 * 8);
                    float4 f0 = ap[0], f1 = ap[1];
                    f[0]=f0.x; f[1]=f0.y; f[2]=f0.z; f[3]=f0.w;
                    f[4]=f1.x; f[5]=f1.y; f[6]=f1.z; f[7]=f1.w;
                } else {
#pragma unroll
                    for (int j = 0; j < 8; j++) f[j] = 0.0f;
                }
                uint32_t hw[4], lw[4];
#pragma unroll
                for (int j = 0; j < 4; j++) {
                    __nv_bfloat16 h0 = __float2bfloat16(f[2*j]);
                    __nv_bfloat16 h1 = __float2bfloat16(f[2*j+1]);
                    float r0 = f[2*j]   - __bfloat162float(h0);
                    float r1 = f[2*j+1] - __bfloat162float(h1);
                    hw[j] = (uint32_t)__bfloat16_as_ushort(h0) |
                            ((uint32_t)__bfloat16_as_ushort(h1) << 16);
                    lw[j] = (uint32_t)__bfloat16_as_ushort(__float2bfloat16(r0)) |
                            ((uint32_t)__bfloat16_as_ushort(__float2bfloat16(r1)) << 16);
                }
                *reinterpret_cast<uint4*>(sAh + row * P + g8 * 8) =
                    make_uint4(hw[0], hw[1], hw[2], hw[3]);
                *reinterpret_cast<uint4*>(sAl + row * P + g8 * 8) =
                    make_uint4(lw[0], lw[1], lw[2], lw[3]);
            }
        }
        // ---- B chunk: N x 64 bf16 hi/lo
        for (int t = tid; t < N * 8; t += 256) {
            int n = t >> 3, g8 = t & 7;
            size_t gofs = (size_t)n * K + k0g + g8 * 8;
            *reinterpret_cast<uint4*>(sBh + n * P + g8 * 8) =
                *reinterpret_cast<const uint4*>(wh + gofs);
            *reinterpret_cast<uint4*>(sBl + n * P + g8 * 8) =
                *reinterpret_cast<const uint4*>(wl + gofs);
        }
        __syncthreads();

#pragma unroll
        for (int ks = 0; ks < 4; ks++) {
            const int k0 = ks * 16;
            uint32_t ah[MT][4], al[MT][4];
#pragma unroll
            for (int mt = 0; mt < MT; mt++) {
                int row = wm * WM + mt * 16 + (lane & 15);
                int kk  = k0 + (lane >> 4) * 8;
                ldmatrix_x4(ah[mt][0], ah[mt][1], ah[mt][2], ah[mt][3],
                            smem_u32(sAh + row * P + kk));
                ldmatrix_x4(al[mt][0], al[mt][1], al[mt][2], al[mt][3],
                            smem_u32(sAl + row * P + kk));
            }
            uint32_t bh[NT][2], bl[NT][2];
#pragma unroll
            for (int nt = 0; nt < NT; nt++) {
                int n = wn * WN + nt * 8 + gid;
                const __nv_bfloat16* ph = sBh + n * P + k0 + tig * 2;
                const __nv_bfloat16* pl = sBl + n * P + k0 + tig * 2;
                bh[nt][0] = *reinterpret_cast<const uint32_t*>(ph);
                bh[nt][1] = *reinterpret_cast<const uint32_t*>(ph + 8);
                bl[nt][0] = *reinterpret_cast<const uint32_t*>(pl);
                bl[nt][1] = *reinterpret_cast<const uint32_t*>(pl + 8);
            }
#pragma unroll
            for (int mt = 0; mt < MT; mt++)
#pragma unroll
                for (int nt = 0; nt < NT; nt++) {
                    mma_bf16(acc[mt][nt], ah[mt], bh[nt]);
                    mma_bf16(acc[mt][nt], ah[mt], bl[nt]);
                    mma_bf16(acc[mt][nt], al[mt], bh[nt]);
                }
        }
        __syncthreads();
    }

    // ---- epilogue: scale rows by g_non, store fp16 messages
#pragma unroll
    for (int mt = 0; mt < MT; mt++) {
        int r0 = m0 + wm * WM + mt * 16 + gid;
        int r1 = r0 + 8;
        float s0 = (r0 < M) ? g_non[r0] : 0.0f;
        float s1 = (r1 < M) ? g_non[r1] : 0.0f;
#pragma unroll
        for (int nt = 0; nt < NT; nt++) {
            int n = wn * WN + nt * 8 + tig * 2;
            if (r0 < M) {
                __half2 o = __floats2half2_rn(acc[mt][nt][0] * s0, acc[mt][nt][1] * s0);
                *reinterpret_cast<__half2*>(g_h + (size_t)r0 * N + n) = o;
            }
            if (r1 < M) {
                __half2 o = __floats2half2_rn(acc[mt][nt][2] * s1, acc[mt][nt][3] * s1);
                *reinterpret_cast<__half2*>(g_h + (size_t)r1 * N + n) = o;
            }
        }
    }
}

// --------------------------- gather-aggregate --------------------------------
// One warp per dst node; MLP=4 unroll; fp32 accumulation.
// Hidden layers: write relu(act) pre-split to g_act_hi/lo (bf16).
// Final layer: write fp32 to outp.

template<int N, bool RELU, bool TO_PARAM>
__global__ void aggregate_kernel(const float* __restrict__ bias,
                                 float* __restrict__ outp, int M) {
    constexpr int VPL = N / 32;   // halfs per lane: 4 (N=128) or 2 (N=64)
    int warp = (blockIdx.x * blockDim.x + threadIdx.x) >> 5;
    if (warp >= M) return;
    int lane = threadIdx.x & 31;

    int beg = g_off[warp];
    int end = beg + g_cin[warp];

    float acc[VPL];
#pragma unroll
    for (int c = 0; c < VPL; c++) acc[c] = 0.0f;

    int e = beg;
    for (; e + 3 < end; e += 4) {   // MLP=4: batch indices, then 4 indep rows
        int s0 = g_csrc[e];
        int s1 = g_csrc[e + 1];
        int s2 = g_csrc[e + 2];
        int s3 = g_csrc[e + 3];
        if (VPL == 4) {
            uint2 u0 = *reinterpret_cast<const uint2*>(g_h + (size_t)s0 * N + lane * 4);
            uint2 u1 = *reinterpret_cast<const uint2*>(g_h + (size_t)s1 * N + lane * 4);
            uint2 u2 = *reinterpret_cast<const uint2*>(g_h + (size_t)s2 * N + lane * 4);
            uint2 u3 = *reinterpret_cast<const uint2*>(g_h + (size_t)s3 * N + lane * 4);
            float2 a, b;
            a = __half22float2(*reinterpret_cast<__half2*>(&u0.x));
            b = __half22float2(*reinterpret_cast<__half2*>(&u0.y));
            acc[0] += a.x; acc[1] += a.y; acc[2] += b.x; acc[3] += b.y;
            a = __half22float2(*reinterpret_cast<__half2*>(&u1.x));
            b = __half22float2(*reinterpret_cast<__half2*>(&u1.y));
            acc[0] += a.x; acc[1] += a.y; acc[2] += b.x; acc[3] += b.y;
            a = __half22float2(*reinterpret_cast<__half2*>(&u2.x));
            b = __half22float2(*reinterpret_cast<__half2*>(&u2.y));
            acc[0] += a.x; acc[1] += a.y; acc[2] += b.x; acc[3] += b.y;
            a = __half22float2(*reinterpret_cast<__half2*>(&u3.x));
            b = __half22float2(*reinterpret_cast<__half2*>(&u3.y));
            acc[0] += a.x; acc[1] += a.y; acc[2] += b.x; acc[3] += b.y;
        } else {
            uint32_t u0 = *reinterpret_cast<const uint32_t*>(g_h + (size_t)s0 * N + lane * 2);
            uint32_t u1 = *reinterpret_cast<const uint32_t*>(g_h + (size_t)s1 * N + lane * 2);
            uint32_t u2 = *reinterpret_cast<const uint32_t*>(g_h + (size_t)s2 * N + lane * 2);
            uint32_t u3 = *reinterpret_cast<const uint32_t*>(g_h + (size_t)s3 * N + lane * 2);
            float2 a;
            a = __half22float2(*reinterpret_cast<__half2*>(&u0)); acc[0] += a.x; acc[1] += a.y;
            a = __half22float2(*reinterpret_cast<__half2*>(&u1)); acc[0] += a.x; acc[1] += a.y;
            a = __half22float2(*reinterpret_cast<__half2*>(&u2)); acc[0] += a.x; acc[1] += a.y;
            a = __half22float2(*reinterpret_cast<__half2*>(&u3)); acc[0] += a.x; acc[1] += a.y;
        }
    }
    for (; e < end; e++) {
        int s0 = g_csrc[e];
        if (VPL == 4) {
            uint2 u0 = *reinterpret_cast<const uint2*>(g_h + (size_t)s0 * N + lane * 4);
            float2 a = __half22float2(*reinterpret_cast<__half2*>(&u0.x));
            float2 b = __half22float2(*reinterpret_cast<__half2*>(&u0.y));
            acc[0] += a.x; acc[1] += a.y; acc[2] += b.x; acc[3] += b.y;
        } else {
            uint32_t u0 = *reinterpret_cast<const uint32_t*>(g_h + (size_t)s0 * N + lane * 2);
            float2 a = __half22float2(*reinterpret_cast<__half2*>(&u0));
            acc[0] += a.x; acc[1] += a.y;
        }
    }

    float s = g_nin[warp];
    if (TO_PARAM) {
        if (VPL == 4) {
            float4 b = reinterpret_cast<const float4*>(bias)[lane];
            float4 o;
            o.x = acc[0] * s + b.x; o.y = acc[1] * s + b.y;
            o.z = acc[2] * s + b.z; o.w = acc[3] * s + b.w;
            if (RELU) {
                o.x = fmaxf(o.x, 0.f); o.y = fmaxf(o.y, 0.f);
                o.z = fmaxf(o.z, 0.f); o.w = fmaxf(o.w, 0.f);
            }
            *reinterpret_cast<float4*>(outp + (size_t)warp * N + lane * 4) = o;
        } else {
            float2 b = reinterpret_cast<const float2*>(bias)[lane];
            float2 o;
            o.x = acc[0] * s + b.x; o.y = acc[1] * s + b.y;
            if (RELU) { o.x = fmaxf(o.x, 0.f); o.y = fmaxf(o.y, 0.f); }
            *reinterpret_cast<float2*>(outp + (size_t)warp * N + lane * 2) = o;
        }
    } else {
        // hidden layer: split to bf16 hi/lo for next GEMM (VPL==4 path, N=128)
        float4 b = reinterpret_cast<const float4*>(bias)[lane];
        float o[4];
        o[0] = acc[0] * s + b.x; o[1] = acc[1] * s + b.y;
        o[2] = acc[2] * s + b.z; o[3] = acc[3] * s + b.w;
        if (RELU) {
#pragma unroll
            for (int j = 0; j < 4; j++) o[j] = fmaxf(o[j], 0.f);
        }
        uint32_t hw[2], lw[2];
#pragma unroll
        for (int j = 0; j < 2; j++) {
            __nv_bfloat16 h0 = __float2bfloat16(o[2*j]);
            __nv_bfloat16 h1 = __float2bfloat16(o[2*j+1]);
            float r0 = o[2*j]   - __bfloat162float(h0);
            float r1 = o[2*j+1] - __bfloat162float(h1);
            hw[j] = (uint32_t)__bfloat16_as_ushort(h0) |
                    ((uint32_t)__bfloat16_as_ushort(h1) << 16);
            lw[j] = (uint32_t)__bfloat16_as_ushort(__float2bfloat16(r0)) |
                    ((uint32_t)__bfloat16_as_ushort(__float2bfloat16(r1)) << 16);
        }
        size_t ofs = (size_t)warp * N + lane * 4;
        *reinterpret_cast<uint2*>(g_act_hi + ofs) = make_uint2(hw[0], hw[1]);
        *reinterpret_cast<uint2*>(g_act_lo + ofs) = make_uint2(lw[0], lw[1]);
    }
}

// --------------------------- launch ------------------------------------------

extern "C" void kernel_launch(void* const* d_in, const int* in_sizes, int n_in,
                              void* d_out, int out_size) {
    const float* x  = (const float*)d_in[0];
    const int*   ei = (const int*)d_in[1];
    const float* W0 = (const float*)d_in[2];
    const float* b0 = (const float*)d_in[3];
    const float* W1 = (const float*)d_in[4];
    const float* b1 = (const float*)d_in[5];
    const float* W2 = (const float*)d_in[6];
    const float* b2 = (const float*)d_in[7];
    const float* W3 = (const float*)d_in[8];
    const float* b3 = (const float*)d_in[9];
    float* out = (float*)d_out;

    const int M = in_sizes[0] / 256;   // 50000
    const int E = in_sizes[1] / 2;     // 800000
    const int T = 256;

    const int dyn128 = (128 + 128) * 72 * 2 * 2;   // 73728
    const int dyn64  = (128 + 64)  * 72 * 2 * 2;   // 55296
    cudaFuncSetAttribute(gemm_mma_kernel<256, 128, false>,
                         cudaFuncAttributeMaxDynamicSharedMemorySize, dyn128);
    cudaFuncSetAttribute(gemm_mma_kernel<128, 128, true>,
                         cudaFuncAttributeMaxDynamicSharedMemorySize, dyn128);
    cudaFuncSetAttribute(gemm_mma_kernel<128, 64, true>,
                         cudaFuncAttributeMaxDynamicSharedMemorySize, dyn64);

    // ---- preprocessing
    zero_counts_kernel<<<(M + T - 1) / T, T>>>(M);
    count_deg_kernel<<<(2 * E + T - 1) / T, T>>>(ei, E);
    norms_alloc_kernel<<<(M + T - 1) / T, T>>>(M);
    fill_csr_kernel<<<(E + T - 1) / T, T>>>(ei, E);
    weight_prep_kernel<<<(WT_TOTAL + T - 1) / T, T>>>(W0, W1, W2, W3);

    const int gemm_blocks = (M + 127) / 128;   // 391
    const int agg_blocks  = (M * 32 + T - 1) / T;

    // ---- layer 0: 256 -> 128, relu
    gemm_mma_kernel<256, 128, false><<<gemm_blocks, 256, dyn128>>>(x, 0, M);
    aggregate_kernel<128, true, false><<<agg_blocks, T>>>(b0, nullptr, M);

    // ---- layer 1: 128 -> 128, relu
    gemm_mma_kernel<128, 128, true><<<gemm_blocks, 256, dyn128>>>(nullptr, 32768, M);
    aggregate_kernel<128, true, false><<<agg_blocks, T>>>(b1, nullptr, M);

    // ---- layer 2: 128 -> 128, relu
    gemm_mma_kernel<128, 128, true><<<gemm_blocks, 256, dyn128>>>(nullptr, 49152, M);
    aggregate_kernel<128, true, false><<<agg_blocks, T>>>(b2, nullptr, M);

    // ---- layer 3: 128 -> 64, no relu, write d_out
    gemm_mma_kernel<128, 64, true><<<gemm_blocks, 256, dyn64>>>(nullptr, 65536, M);
    aggregate_kernel<64, false, true><<<agg_blocks, T>>>(b3, out, M);
}